// round 9
// baseline (speedup 1.0000x reference)
#include <cuda_runtime.h>
#include <cuda_bf16.h>
#include <cstdint>

#define BB 32
#define TT 256
#define CC 512
#define LL 25
#define MM (BB*TT)   // 8192

// Scratch (device globals — no runtime allocation allowed)
__device__ float g_wf[(size_t)MM * CC];            // 16 MB
__device__ float g_scores[(size_t)BB * LL * TT];   // 0.8 MB
__device__ float g_part[(size_t)8 * BB * LL * CC]; // 13 MB pvam partials
__device__ __align__(16) __nv_bfloat16 g_Xh[(size_t)MM * CC];
__device__ __align__(16) __nv_bfloat16 g_Xl[(size_t)MM * CC];
__device__ __align__(16) __nv_bfloat16 g_Wh[(size_t)CC * CC];
__device__ __align__(16) __nv_bfloat16 g_Wl[(size_t)CC * CC];

// ---------------------------------------------------------------------------
// Helpers
// ---------------------------------------------------------------------------
__device__ __forceinline__ uint32_t smem_u32(const void* p) {
    uint32_t a;
    asm("{ .reg .u64 t; cvta.to.shared.u64 t, %1; cvt.u32.u64 %0, t; }"
        : "=r"(a) : "l"(p));
    return a;
}
__device__ __forceinline__ void ldsm4(uint32_t* r, uint32_t addr) {
    asm volatile("ldmatrix.sync.aligned.m8n8.x4.shared.b16 {%0,%1,%2,%3}, [%4];"
                 : "=r"(r[0]), "=r"(r[1]), "=r"(r[2]), "=r"(r[3]) : "r"(addr));
}
__device__ __forceinline__ void mma16816(float* d, const uint32_t* a,
                                         uint32_t b0, uint32_t b1) {
    asm volatile(
        "mma.sync.aligned.m16n8k16.row.col.f32.bf16.bf16.f32 "
        "{%0,%1,%2,%3}, {%4,%5,%6,%7}, {%8,%9}, {%0,%1,%2,%3};"
        : "+f"(d[0]), "+f"(d[1]), "+f"(d[2]), "+f"(d[3])
        : "r"(a[0]), "r"(a[1]), "r"(a[2]), "r"(a[3]), "r"(b0), "r"(b1));
}
// fp32 -> bf16 hi + bf16 lo (residual), packed as bf16x2 words
__device__ __forceinline__ void cvt2(float4 v, uint2& hi, uint2& lo) {
    __nv_bfloat162 h01 = __floats2bfloat162_rn(v.x, v.y);
    __nv_bfloat162 h23 = __floats2bfloat162_rn(v.z, v.w);
    float2 f01 = __bfloat1622float2(h01);
    float2 f23 = __bfloat1622float2(h23);
    __nv_bfloat162 l01 = __floats2bfloat162_rn(v.x - f01.x, v.y - f01.y);
    __nv_bfloat162 l23 = __floats2bfloat162_rn(v.z - f23.x, v.w - f23.y);
    hi.x = *reinterpret_cast<uint32_t*>(&h01);
    hi.y = *reinterpret_cast<uint32_t*>(&h23);
    lo.x = *reinterpret_cast<uint32_t*>(&l01);
    lo.y = *reinterpret_cast<uint32_t*>(&l23);
}

// ---------------------------------------------------------------------------
// Kernel 0: fp32 -> bf16 hi/lo prepass (globals referenced in device code only
// — host-passed __device__ symbols hit the ATS host-shadow bug).
// ---------------------------------------------------------------------------
__global__ __launch_bounds__(256) void k_cvtX(const float* __restrict__ src) {
    const size_t i = (size_t)blockIdx.x * 256 + threadIdx.x;
    float4 v = ((const float4*)src)[i];
    uint2 h, l;
    cvt2(v, h, l);
    ((uint2*)g_Xh)[i] = h;
    ((uint2*)g_Xl)[i] = l;
}
__global__ __launch_bounds__(256) void k_cvtW(const float* __restrict__ src) {
    const size_t i = (size_t)blockIdx.x * 256 + threadIdx.x;
    float4 v = ((const float4*)src)[i];
    uint2 h, l;
    cvt2(v, h, l);
    ((uint2*)g_Wh)[i] = h;
    ((uint2*)g_Wl)[i] = l;
}

// ---------------------------------------------------------------------------
// Kernel 1: wf = X @ W^T + bias via mma.sync bf16 hi/lo split (3 passes).
// Proven structure: BM=BN=128, BK=32, 8 warps 4(m)x2(n), LDT=40.
// ---------------------------------------------------------------------------
#define LDT 40

__global__ __launch_bounds__(256) void k_gemm_mma(const float* __restrict__ bias) {
    __shared__ __align__(16) __nv_bfloat16 sAh[128 * LDT];
    __shared__ __align__(16) __nv_bfloat16 sAl[128 * LDT];
    __shared__ __align__(16) __nv_bfloat16 sBh[128 * LDT];
    __shared__ __align__(16) __nv_bfloat16 sBl[128 * LDT];

    const int tid = threadIdx.x, lane = tid & 31, wid = tid >> 5;
    const int m0 = blockIdx.y * 128, n0 = blockIdx.x * 128;
    const int wm = (wid >> 1) * 32, wn = (wid & 1) * 64;

    const uint32_t sAh_b = smem_u32(sAh), sAl_b = smem_u32(sAl);
    const uint32_t sBh_b = smem_u32(sBh), sBl_b = smem_u32(sBl);

    const int lr = lane & 15, kc = (lane >> 4) << 3;
    const uint32_t a_l = (uint32_t)(((wm + lr) * LDT + kc) * 2);
    const int br = (lane & 7) + ((lane >> 4) << 3);
    const int bk = ((lane >> 3) & 1) << 3;
    const uint32_t b_l = (uint32_t)(((wn + br) * LDT + bk) * 2);

    float acc[2][8][4];
#pragma unroll
    for (int i = 0; i < 2; i++)
#pragma unroll
        for (int j = 0; j < 8; j++)
#pragma unroll
            for (int q = 0; q < 4; q++) acc[i][j][q] = 0.f;

#pragma unroll 1
    for (int ch = 0; ch < 16; ch++) {
        const int k0 = ch * 32;
#pragma unroll
        for (int it = 0; it < 4; it++) {
            const int idx = it * 256 + tid;
            const int r = idx >> 3, c = idx & 7;
            const size_t gx = (size_t)(m0 + r) * CC + k0 + c * 4;
            const size_t gw = (size_t)(n0 + r) * CC + k0 + c * 4;
            *(uint2*)&sAh[r * LDT + c * 4] = *(const uint2*)&g_Xh[gx];
            *(uint2*)&sAl[r * LDT + c * 4] = *(const uint2*)&g_Xl[gx];
            *(uint2*)&sBh[r * LDT + c * 4] = *(const uint2*)&g_Wh[gw];
            *(uint2*)&sBl[r * LDT + c * 4] = *(const uint2*)&g_Wl[gw];
        }
        __syncthreads();

#pragma unroll
        for (int s = 0; s < 2; s++) {
            uint32_t Ah[2][4], Al[2][4];
#pragma unroll
            for (int i = 0; i < 2; i++) {
                const uint32_t off = a_l + (uint32_t)(i * 16 * LDT * 2 + s * 32);
                ldsm4(Ah[i], sAh_b + off);
                ldsm4(Al[i], sAl_b + off);
            }
#pragma unroll
            for (int g = 0; g < 4; g++) {
                const uint32_t off = b_l + (uint32_t)(g * 16 * LDT * 2 + s * 32);
                uint32_t Bh[4], Bl[4];
                ldsm4(Bh, sBh_b + off);
                ldsm4(Bl, sBl_b + off);
#pragma unroll
                for (int i = 0; i < 2; i++) {
                    mma16816(acc[i][2 * g],     Ah[i], Bh[0], Bh[1]);
                    mma16816(acc[i][2 * g + 1], Ah[i], Bh[2], Bh[3]);
                    mma16816(acc[i][2 * g],     Ah[i], Bl[0], Bl[1]);
                    mma16816(acc[i][2 * g + 1], Ah[i], Bl[2], Bl[3]);
                    mma16816(acc[i][2 * g],     Al[i], Bh[0], Bh[1]);
                    mma16816(acc[i][2 * g + 1], Al[i], Bh[2], Bh[3]);
                }
            }
        }
        __syncthreads();
    }

    const int cr = lane >> 2, cc2 = (lane & 3) * 2;
#pragma unroll
    for (int i = 0; i < 2; i++) {
        const int m = m0 + wm + i * 16 + cr;
#pragma unroll
        for (int j = 0; j < 8; j++) {
            const int n = n0 + wn + j * 8 + cc2;
            float2 bv = *(const float2*)&bias[n];
            *(float2*)&g_wf[(size_t)m * CC + n] =
                make_float2(acc[i][j][0] + bv.x, acc[i][j][1] + bv.y);
            *(float2*)&g_wf[(size_t)(m + 8) * CC + n] =
                make_float2(acc[i][j][2] + bv.x, acc[i][j][3] + bv.y);
        }
    }
}

// ---------------------------------------------------------------------------
// Kernel 2: scores[b,l,t] = sum_c tanh(wf[b,t,c] + pos[l,c]) * aw[c]
// R7 geometry (grid (B,8,2), 256 thr, wf rows in regs, pos tile in smem) but
// with DEFERRED reductions: accumulate all nl l-sums first, then run the 13
// butterfly trees interleaved (ILP hides the 5x26cyc SHFL chain latency).
// atten_b dropped (softmax shift-invariant).
// ---------------------------------------------------------------------------
__device__ __forceinline__ float tanh_hw(float x) {
    float y;
    asm("tanh.approx.f32 %0, %1;" : "=f"(y) : "f"(x));
    return y;
}

__global__ __launch_bounds__(256) void k_scores(const float* __restrict__ pos,
                                                const float* __restrict__ aw) {
    __shared__ __align__(16) float sp[13 * CC];

    const int tid = threadIdx.x;
    const int b = blockIdx.x;
    const int tch = blockIdx.y;
    const int l0 = blockIdx.z * 13;
    const int nl = blockIdx.z ? 12 : 13;
    const int warp = tid >> 5, lane = tid & 31;

    for (int i = tid; i < nl * CC; i += 256) sp[i] = pos[l0 * CC + i];
    __syncthreads();

    float4 wv[4];
#pragma unroll
    for (int g = 0; g < 4; g++)
        wv[g] = *(const float4*)&aw[g * 128 + lane * 4];

    for (int tt = 0; tt < 4; tt++) {
        const int t = tch * 32 + warp * 4 + tt;
        const float* wrow = &g_wf[((size_t)b * TT + t) * CC];
        float4 fv[4];
#pragma unroll
        for (int g = 0; g < 4; g++)
            fv[g] = *(const float4*)&wrow[g * 128 + lane * 4];

        float acc[13];
#pragma unroll
        for (int l = 0; l < 13; l++) acc[l] = 0.f;

        for (int l = 0; l < nl; l++) {
            float a = 0.f;
#pragma unroll
            for (int g = 0; g < 4; g++) {
                float4 p = *(const float4*)&sp[l * CC + g * 128 + lane * 4];
                a += tanh_hw(fv[g].x + p.x) * wv[g].x;
                a += tanh_hw(fv[g].y + p.y) * wv[g].y;
                a += tanh_hw(fv[g].z + p.z) * wv[g].z;
                a += tanh_hw(fv[g].w + p.w) * wv[g].w;
            }
            acc[l] = a;
        }

        // Interleaved butterfly trees: 13 independent chains -> latency hidden
#pragma unroll
        for (int o = 16; o > 0; o >>= 1)
#pragma unroll
            for (int l = 0; l < 13; l++)
                acc[l] += __shfl_xor_sync(0xFFFFFFFFu, acc[l], o);

        float* srow = &g_scores[((size_t)b * LL + l0) * TT + t];
#pragma unroll
        for (int l = 0; l < 13; l++)
            if (l < nl && lane == l)
                srow[(size_t)l * TT] = acc[l];
    }
}

// ---------------------------------------------------------------------------
// Kernel 3: in-place softmax over t.
// ---------------------------------------------------------------------------
__global__ __launch_bounds__(256) void k_softmax() {
    __shared__ float red[8];
    __shared__ float red2[8];
    const int row = blockIdx.x;
    float* s = g_scores + (size_t)row * TT;
    const int tid = threadIdx.x, lane = tid & 31, w = tid >> 5;

    float v = s[tid];
    float m = v;
#pragma unroll
    for (int o = 16; o > 0; o >>= 1)
        m = fmaxf(m, __shfl_xor_sync(0xFFFFFFFFu, m, o));
    if (lane == 0) red[w] = m;
    __syncthreads();
    float bm = red[0];
#pragma unroll
    for (int i = 1; i < 8; i++) bm = fmaxf(bm, red[i]);

    float e = __expf(v - bm);
    float sum = e;
#pragma unroll
    for (int o = 16; o > 0; o >>= 1)
        sum += __shfl_xor_sync(0xFFFFFFFFu, sum, o);
    if (lane == 0) red2[w] = sum;
    __syncthreads();
    float tot = 0.f;
#pragma unroll
    for (int i = 0; i < 8; i++) tot += red2[i];

    s[tid] = e / tot;
}

// ---------------------------------------------------------------------------
// Kernel 4a: pvam partials, 8-way t-split, float2 lanes + packed f32x2 FMA.
// grid (B, 8), 256 threads; thread handles c = {2*tid, 2*tid+1}.
// ---------------------------------------------------------------------------
__global__ __launch_bounds__(256) void k_pvam1() {
    __shared__ __align__(8) float2 at2[LL][32];   // (a,a) pairs
    const int b = blockIdx.x, s = blockIdx.y;
    const int tid = threadIdx.x;

    for (int i = tid; i < LL * 32; i += 256) {
        const int l = i >> 5, j = i & 31;
        const float a = g_scores[((size_t)b * LL + l) * TT + s * 32 + j];
        at2[l][j] = make_float2(a, a);
    }
    __syncthreads();

    unsigned long long acc[LL];
#pragma unroll
    for (int l = 0; l < LL; l++) acc[l] = 0ull;

    const unsigned long long* at2u = (const unsigned long long*)at2;
    const unsigned long long* wb = (const unsigned long long*)
        (&g_wf[((size_t)b * TT + s * 32) * CC]) + tid;

#pragma unroll 4
    for (int j = 0; j < 32; j++) {
        const unsigned long long v = wb[(size_t)j * (CC / 2)];
#pragma unroll
        for (int l = 0; l < LL; l++)
            asm("fma.rn.f32x2 %0, %1, %2, %0;"
                : "+l"(acc[l]) : "l"(at2u[l * 32 + j]), "l"(v));
    }

    unsigned long long* pp = (unsigned long long*)
        (&g_part[(size_t)s * BB * LL * CC + (size_t)b * LL * CC]) + tid;
#pragma unroll
    for (int l = 0; l < LL; l++) pp[(size_t)l * (CC / 2)] = acc[l];
}

// Kernel 4b: sum the 8 partials -> out.
__global__ __launch_bounds__(256) void k_pvam2(float* __restrict__ out) {
    const size_t N = (size_t)BB * LL * CC;
    size_t i = (size_t)blockIdx.x * 256 + threadIdx.x;
    float a = 0.f;
#pragma unroll
    for (int s = 0; s < 8; s++) a += g_part[s * N + i];
    out[i] = a;
}

// ---------------------------------------------------------------------------
extern "C" void kernel_launch(void* const* d_in, const int* in_sizes, int n_in,
                              void* d_out, int out_size) {
    const float* X    = (const float*)d_in[0];
    const float* W    = (const float*)d_in[1];
    const float* bias = (const float*)d_in[2];
    const float* pos  = (const float*)d_in[3];
    const float* aw   = (const float*)d_in[4];
    float* out = (float*)d_out;

    k_cvtX<<<MM * CC / 4 / 256, 256>>>(X);
    k_cvtW<<<CC * CC / 4 / 256, 256>>>(W);
    k_gemm_mma<<<dim3(CC / 128, MM / 128), 256>>>(bias);
    k_scores<<<dim3(BB, TT / 32, 2), 256>>>(pos, aw);
    k_softmax<<<BB * LL, 256>>>();
    k_pvam1<<<dim3(BB, 8), 256>>>();
    k_pvam2<<<BB * LL * CC / 256, 256>>>(out);
}

// round 11
// speedup vs baseline: 1.1927x; 1.1927x over previous
#include <cuda_runtime.h>
#include <cuda_bf16.h>
#include <cstdint>

#define BB 32
#define TT 256
#define CC 512
#define LL 25
#define MM (BB*TT)   // 8192

// Scratch (device globals — no runtime allocation allowed)
__device__ float g_wf[(size_t)MM * CC];            // 16 MB
__device__ float g_scores[(size_t)BB * LL * TT];   // 0.8 MB
__device__ float g_part[(size_t)8 * BB * LL * CC]; // 13 MB pvam partials
__device__ __align__(16) __nv_bfloat16 g_Xh[(size_t)MM * CC];
__device__ __align__(16) __nv_bfloat16 g_Xl[(size_t)MM * CC];
__device__ __align__(16) __nv_bfloat16 g_Wh[(size_t)CC * CC];
__device__ __align__(16) __nv_bfloat16 g_Wl[(size_t)CC * CC];

// ---------------------------------------------------------------------------
// Helpers
// ---------------------------------------------------------------------------
__device__ __forceinline__ uint32_t smem_u32(const void* p) {
    uint32_t a;
    asm("{ .reg .u64 t; cvta.to.shared.u64 t, %1; cvt.u32.u64 %0, t; }"
        : "=r"(a) : "l"(p));
    return a;
}
__device__ __forceinline__ void ldsm4(uint32_t* r, uint32_t addr) {
    asm volatile("ldmatrix.sync.aligned.m8n8.x4.shared.b16 {%0,%1,%2,%3}, [%4];"
                 : "=r"(r[0]), "=r"(r[1]), "=r"(r[2]), "=r"(r[3]) : "r"(addr));
}
__device__ __forceinline__ void mma16816(float* d, const uint32_t* a,
                                         uint32_t b0, uint32_t b1) {
    asm volatile(
        "mma.sync.aligned.m16n8k16.row.col.f32.bf16.bf16.f32 "
        "{%0,%1,%2,%3}, {%4,%5,%6,%7}, {%8,%9}, {%0,%1,%2,%3};"
        : "+f"(d[0]), "+f"(d[1]), "+f"(d[2]), "+f"(d[3])
        : "r"(a[0]), "r"(a[1]), "r"(a[2]), "r"(a[3]), "r"(b0), "r"(b1));
}
// fp32 -> bf16 hi + bf16 lo (residual), packed as bf16x2 words
__device__ __forceinline__ void cvt2(float4 v, uint2& hi, uint2& lo) {
    __nv_bfloat162 h01 = __floats2bfloat162_rn(v.x, v.y);
    __nv_bfloat162 h23 = __floats2bfloat162_rn(v.z, v.w);
    float2 f01 = __bfloat1622float2(h01);
    float2 f23 = __bfloat1622float2(h23);
    __nv_bfloat162 l01 = __floats2bfloat162_rn(v.x - f01.x, v.y - f01.y);
    __nv_bfloat162 l23 = __floats2bfloat162_rn(v.z - f23.x, v.w - f23.y);
    hi.x = *reinterpret_cast<uint32_t*>(&h01);
    hi.y = *reinterpret_cast<uint32_t*>(&h23);
    lo.x = *reinterpret_cast<uint32_t*>(&l01);
    lo.y = *reinterpret_cast<uint32_t*>(&l23);
}

// ---------------------------------------------------------------------------
// Kernel 0: fp32 -> bf16 hi/lo prepass (globals referenced in device code only
// — host-passed __device__ symbols hit the ATS host-shadow bug).
// ---------------------------------------------------------------------------
__global__ __launch_bounds__(256) void k_cvtX(const float* __restrict__ src) {
    const size_t i = (size_t)blockIdx.x * 256 + threadIdx.x;
    float4 v = ((const float4*)src)[i];
    uint2 h, l;
    cvt2(v, h, l);
    ((uint2*)g_Xh)[i] = h;
    ((uint2*)g_Xl)[i] = l;
}
__global__ __launch_bounds__(256) void k_cvtW(const float* __restrict__ src) {
    const size_t i = (size_t)blockIdx.x * 256 + threadIdx.x;
    float4 v = ((const float4*)src)[i];
    uint2 h, l;
    cvt2(v, h, l);
    ((uint2*)g_Wh)[i] = h;
    ((uint2*)g_Wl)[i] = l;
}

// ---------------------------------------------------------------------------
// Kernel 1: wf = X @ W^T + bias via mma.sync bf16 hi/lo split (3 passes).
// Proven structure: BM=BN=128, BK=32, 8 warps 4(m)x2(n), LDT=40.
// ---------------------------------------------------------------------------
#define LDT 40

__global__ __launch_bounds__(256) void k_gemm_mma(const float* __restrict__ bias) {
    __shared__ __align__(16) __nv_bfloat16 sAh[128 * LDT];
    __shared__ __align__(16) __nv_bfloat16 sAl[128 * LDT];
    __shared__ __align__(16) __nv_bfloat16 sBh[128 * LDT];
    __shared__ __align__(16) __nv_bfloat16 sBl[128 * LDT];

    const int tid = threadIdx.x, lane = tid & 31, wid = tid >> 5;
    const int m0 = blockIdx.y * 128, n0 = blockIdx.x * 128;
    const int wm = (wid >> 1) * 32, wn = (wid & 1) * 64;

    const uint32_t sAh_b = smem_u32(sAh), sAl_b = smem_u32(sAl);
    const uint32_t sBh_b = smem_u32(sBh), sBl_b = smem_u32(sBl);

    const int lr = lane & 15, kc = (lane >> 4) << 3;
    const uint32_t a_l = (uint32_t)(((wm + lr) * LDT + kc) * 2);
    const int br = (lane & 7) + ((lane >> 4) << 3);
    const int bk = ((lane >> 3) & 1) << 3;
    const uint32_t b_l = (uint32_t)(((wn + br) * LDT + bk) * 2);

    float acc[2][8][4];
#pragma unroll
    for (int i = 0; i < 2; i++)
#pragma unroll
        for (int j = 0; j < 8; j++)
#pragma unroll
            for (int q = 0; q < 4; q++) acc[i][j][q] = 0.f;

#pragma unroll 1
    for (int ch = 0; ch < 16; ch++) {
        const int k0 = ch * 32;
#pragma unroll
        for (int it = 0; it < 4; it++) {
            const int idx = it * 256 + tid;
            const int r = idx >> 3, c = idx & 7;
            const size_t gx = (size_t)(m0 + r) * CC + k0 + c * 4;
            const size_t gw = (size_t)(n0 + r) * CC + k0 + c * 4;
            *(uint2*)&sAh[r * LDT + c * 4] = *(const uint2*)&g_Xh[gx];
            *(uint2*)&sAl[r * LDT + c * 4] = *(const uint2*)&g_Xl[gx];
            *(uint2*)&sBh[r * LDT + c * 4] = *(const uint2*)&g_Wh[gw];
            *(uint2*)&sBl[r * LDT + c * 4] = *(const uint2*)&g_Wl[gw];
        }
        __syncthreads();

#pragma unroll
        for (int s = 0; s < 2; s++) {
            uint32_t Ah[2][4], Al[2][4];
#pragma unroll
            for (int i = 0; i < 2; i++) {
                const uint32_t off = a_l + (uint32_t)(i * 16 * LDT * 2 + s * 32);
                ldsm4(Ah[i], sAh_b + off);
                ldsm4(Al[i], sAl_b + off);
            }
#pragma unroll
            for (int g = 0; g < 4; g++) {
                const uint32_t off = b_l + (uint32_t)(g * 16 * LDT * 2 + s * 32);
                uint32_t Bh[4], Bl[4];
                ldsm4(Bh, sBh_b + off);
                ldsm4(Bl, sBl_b + off);
#pragma unroll
                for (int i = 0; i < 2; i++) {
                    mma16816(acc[i][2 * g],     Ah[i], Bh[0], Bh[1]);
                    mma16816(acc[i][2 * g + 1], Ah[i], Bh[2], Bh[3]);
                    mma16816(acc[i][2 * g],     Ah[i], Bl[0], Bl[1]);
                    mma16816(acc[i][2 * g + 1], Ah[i], Bl[2], Bl[3]);
                    mma16816(acc[i][2 * g],     Al[i], Bh[0], Bh[1]);
                    mma16816(acc[i][2 * g + 1], Al[i], Bh[2], Bh[3]);
                }
            }
        }
        __syncthreads();
    }

    const int cr = lane >> 2, cc2 = (lane & 3) * 2;
#pragma unroll
    for (int i = 0; i < 2; i++) {
        const int m = m0 + wm + i * 16 + cr;
#pragma unroll
        for (int j = 0; j < 8; j++) {
            const int n = n0 + wn + j * 8 + cc2;
            float2 bv = *(const float2*)&bias[n];
            *(float2*)&g_wf[(size_t)m * CC + n] =
                make_float2(acc[i][j][0] + bv.x, acc[i][j][1] + bv.y);
            *(float2*)&g_wf[(size_t)(m + 8) * CC + n] =
                make_float2(acc[i][j][2] + bv.x, acc[i][j][3] + bv.y);
        }
    }
}

// ---------------------------------------------------------------------------
// Kernel 2: scores[b,l,t] = sum_c tanh(wf[b,t,c] + pos[l,c]) * aw[c]
// R7 geometry (grid (B,8,2), 256 thr) + GROUP-4 deferred reductions:
// 4 independent l-accumulators (bounded regs), then 4 interleaved butterfly
// trees (ILP-4 hides SHFL latency). pos tile padded to 16 rows (OOB-safe).
// atten_b dropped (softmax shift-invariant).
// ---------------------------------------------------------------------------
__device__ __forceinline__ float tanh_hw(float x) {
    float y;
    asm("tanh.approx.f32 %0, %1;" : "=f"(y) : "f"(x));
    return y;
}

__global__ __launch_bounds__(256) void k_scores(const float* __restrict__ pos,
                                                const float* __restrict__ aw) {
    __shared__ __align__(16) float sp[16 * CC];   // 32 KB (rows >= nl garbage-ok)

    const int tid = threadIdx.x;
    const int b = blockIdx.x;
    const int tch = blockIdx.y;
    const int l0 = blockIdx.z * 13;
    const int nl = blockIdx.z ? 12 : 13;
    const int warp = tid >> 5, lane = tid & 31;

    for (int i = tid; i < nl * CC; i += 256) sp[i] = pos[l0 * CC + i];
    __syncthreads();

    float4 wv[4];
#pragma unroll
    for (int g = 0; g < 4; g++)
        wv[g] = *(const float4*)&aw[g * 128 + lane * 4];

    for (int tt = 0; tt < 4; tt++) {
        const int t = tch * 32 + warp * 4 + tt;
        const float* wrow = &g_wf[((size_t)b * TT + t) * CC];
        float4 fv[4];
#pragma unroll
        for (int g = 0; g < 4; g++)
            fv[g] = *(const float4*)&wrow[g * 128 + lane * 4];

        float* srow = &g_scores[((size_t)b * LL + l0) * TT + t];

#pragma unroll 1
        for (int lg = 0; lg < nl; lg += 4) {
            float acc[4] = {0.f, 0.f, 0.f, 0.f};
#pragma unroll
            for (int u = 0; u < 4; u++) {
                const float* prow = &sp[(lg + u) * CC];   // rows 13..15 = junk, never stored
                float a = 0.f;
#pragma unroll
                for (int g = 0; g < 4; g++) {
                    float4 p = *(const float4*)&prow[g * 128 + lane * 4];
                    a += tanh_hw(fv[g].x + p.x) * wv[g].x;
                    a += tanh_hw(fv[g].y + p.y) * wv[g].y;
                    a += tanh_hw(fv[g].z + p.z) * wv[g].z;
                    a += tanh_hw(fv[g].w + p.w) * wv[g].w;
                }
                acc[u] = a;
            }
            // 4 interleaved butterfly trees
#pragma unroll
            for (int o = 16; o > 0; o >>= 1)
#pragma unroll
                for (int u = 0; u < 4; u++)
                    acc[u] += __shfl_xor_sync(0xFFFFFFFFu, acc[u], o);
#pragma unroll
            for (int u = 0; u < 4; u++)
                if (lg + u < nl && lane == u)
                    srow[(size_t)(lg + u) * TT] = acc[u];
        }
    }
}

// ---------------------------------------------------------------------------
// Kernel 3: in-place softmax over t.
// ---------------------------------------------------------------------------
__global__ __launch_bounds__(256) void k_softmax() {
    __shared__ float red[8];
    __shared__ float red2[8];
    const int row = blockIdx.x;
    float* s = g_scores + (size_t)row * TT;
    const int tid = threadIdx.x, lane = tid & 31, w = tid >> 5;

    float v = s[tid];
    float m = v;
#pragma unroll
    for (int o = 16; o > 0; o >>= 1)
        m = fmaxf(m, __shfl_xor_sync(0xFFFFFFFFu, m, o));
    if (lane == 0) red[w] = m;
    __syncthreads();
    float bm = red[0];
#pragma unroll
    for (int i = 1; i < 8; i++) bm = fmaxf(bm, red[i]);

    float e = __expf(v - bm);
    float sum = e;
#pragma unroll
    for (int o = 16; o > 0; o >>= 1)
        sum += __shfl_xor_sync(0xFFFFFFFFu, sum, o);
    if (lane == 0) red2[w] = sum;
    __syncthreads();
    float tot = 0.f;
#pragma unroll
    for (int i = 0; i < 8; i++) tot += red2[i];

    s[tid] = e / tot;
}

// ---------------------------------------------------------------------------
// Kernel 4a: pvam partials, 8-way t-split, float2 lanes + packed f32x2 FMA.
// grid (B, 8), 256 threads; thread handles c = {2*tid, 2*tid+1}.
// ---------------------------------------------------------------------------
__global__ __launch_bounds__(256) void k_pvam1() {
    __shared__ __align__(8) float2 at2[LL][32];   // (a,a) pairs
    const int b = blockIdx.x, s = blockIdx.y;
    const int tid = threadIdx.x;

    for (int i = tid; i < LL * 32; i += 256) {
        const int l = i >> 5, j = i & 31;
        const float a = g_scores[((size_t)b * LL + l) * TT + s * 32 + j];
        at2[l][j] = make_float2(a, a);
    }
    __syncthreads();

    unsigned long long acc[LL];
#pragma unroll
    for (int l = 0; l < LL; l++) acc[l] = 0ull;

    const unsigned long long* at2u = (const unsigned long long*)at2;
    const unsigned long long* wb = (const unsigned long long*)
        (&g_wf[((size_t)b * TT + s * 32) * CC]) + tid;

#pragma unroll 4
    for (int j = 0; j < 32; j++) {
        const unsigned long long v = wb[(size_t)j * (CC / 2)];
#pragma unroll
        for (int l = 0; l < LL; l++)
            asm("fma.rn.f32x2 %0, %1, %2, %0;"
                : "+l"(acc[l]) : "l"(at2u[l * 32 + j]), "l"(v));
    }

    unsigned long long* pp = (unsigned long long*)
        (&g_part[(size_t)s * BB * LL * CC + (size_t)b * LL * CC]) + tid;
#pragma unroll
    for (int l = 0; l < LL; l++) pp[(size_t)l * (CC / 2)] = acc[l];
}

// Kernel 4b: sum the 8 partials -> out.
__global__ __launch_bounds__(256) void k_pvam2(float* __restrict__ out) {
    const size_t N = (size_t)BB * LL * CC;
    size_t i = (size_t)blockIdx.x * 256 + threadIdx.x;
    float a = 0.f;
#pragma unroll
    for (int s = 0; s < 8; s++) a += g_part[s * N + i];
    out[i] = a;
}

// ---------------------------------------------------------------------------
extern "C" void kernel_launch(void* const* d_in, const int* in_sizes, int n_in,
                              void* d_out, int out_size) {
    const float* X    = (const float*)d_in[0];
    const float* W    = (const float*)d_in[1];
    const float* bias = (const float*)d_in[2];
    const float* pos  = (const float*)d_in[3];
    const float* aw   = (const float*)d_in[4];
    float* out = (float*)d_out;

    k_cvtX<<<MM * CC / 4 / 256, 256>>>(X);
    k_cvtW<<<CC * CC / 4 / 256, 256>>>(W);
    k_gemm_mma<<<dim3(CC / 128, MM / 128), 256>>>(bias);
    k_scores<<<dim3(BB, TT / 32, 2), 256>>>(pos, aw);
    k_softmax<<<BB * LL, 256>>>();
    k_pvam1<<<dim3(BB, 8), 256>>>();
    k_pvam2<<<BB * LL * CC / 256, 256>>>(out);
}

// round 14
// speedup vs baseline: 1.2251x; 1.0272x over previous
#include <cuda_runtime.h>
#include <cuda_bf16.h>
#include <cstdint>

#define BB 32
#define TT 256
#define CC 512
#define LL 25
#define MM (BB*TT)   // 8192

// Scratch (device globals — no runtime allocation allowed)
__device__ float g_wf[(size_t)MM * CC];            // 16 MB
__device__ float g_scores[(size_t)BB * LL * TT];   // 0.8 MB
__device__ float g_part[(size_t)8 * BB * LL * CC]; // 13 MB pvam partials
__device__ __align__(16) __nv_bfloat16 g_Xh[(size_t)MM * CC];
__device__ __align__(16) __nv_bfloat16 g_Xl[(size_t)MM * CC];
__device__ __align__(16) __nv_bfloat16 g_Wh[(size_t)CC * CC];
__device__ __align__(16) __nv_bfloat16 g_Wl[(size_t)CC * CC];

// ---------------------------------------------------------------------------
// Helpers
// ---------------------------------------------------------------------------
__device__ __forceinline__ uint32_t smem_u32(const void* p) {
    uint32_t a;
    asm("{ .reg .u64 t; cvta.to.shared.u64 t, %1; cvt.u32.u64 %0, t; }"
        : "=r"(a) : "l"(p));
    return a;
}
__device__ __forceinline__ void ldsm4(uint32_t* r, uint32_t addr) {
    asm volatile("ldmatrix.sync.aligned.m8n8.x4.shared.b16 {%0,%1,%2,%3}, [%4];"
                 : "=r"(r[0]), "=r"(r[1]), "=r"(r[2]), "=r"(r[3]) : "r"(addr));
}
__device__ __forceinline__ void mma16816(float* d, const uint32_t* a,
                                         uint32_t b0, uint32_t b1) {
    asm volatile(
        "mma.sync.aligned.m16n8k16.row.col.f32.bf16.bf16.f32 "
        "{%0,%1,%2,%3}, {%4,%5,%6,%7}, {%8,%9}, {%0,%1,%2,%3};"
        : "+f"(d[0]), "+f"(d[1]), "+f"(d[2]), "+f"(d[3])
        : "r"(a[0]), "r"(a[1]), "r"(a[2]), "r"(a[3]), "r"(b0), "r"(b1));
}
__device__ __forceinline__ void cpa16(uint32_t s, const void* g) {
    asm volatile("cp.async.cg.shared.global [%0], [%1], 16;"
                 :: "r"(s), "l"(g) : "memory");
}
#define CPA_COMMIT() asm volatile("cp.async.commit_group;" ::: "memory")
#define CPA_WAIT(n)  asm volatile("cp.async.wait_group %0;" :: "n"(n) : "memory")

// fp32 -> bf16 hi + bf16 lo (residual), packed as bf16x2 words
__device__ __forceinline__ void cvt2(float4 v, uint2& hi, uint2& lo) {
    __nv_bfloat162 h01 = __floats2bfloat162_rn(v.x, v.y);
    __nv_bfloat162 h23 = __floats2bfloat162_rn(v.z, v.w);
    float2 f01 = __bfloat1622float2(h01);
    float2 f23 = __bfloat1622float2(h23);
    __nv_bfloat162 l01 = __floats2bfloat162_rn(v.x - f01.x, v.y - f01.y);
    __nv_bfloat162 l23 = __floats2bfloat162_rn(v.z - f23.x, v.w - f23.y);
    hi.x = *reinterpret_cast<uint32_t*>(&h01);
    hi.y = *reinterpret_cast<uint32_t*>(&h23);
    lo.x = *reinterpret_cast<uint32_t*>(&l01);
    lo.y = *reinterpret_cast<uint32_t*>(&l23);
}

// ---------------------------------------------------------------------------
// Kernel 0: fp32 -> bf16 hi/lo prepass (globals referenced in device code only
// — host-passed __device__ symbols hit the ATS host-shadow bug).
// ---------------------------------------------------------------------------
__global__ __launch_bounds__(256) void k_cvtX(const float* __restrict__ src) {
    const size_t i = (size_t)blockIdx.x * 256 + threadIdx.x;
    float4 v = ((const float4*)src)[i];
    uint2 h, l;
    cvt2(v, h, l);
    ((uint2*)g_Xh)[i] = h;
    ((uint2*)g_Xl)[i] = l;
}
__global__ __launch_bounds__(256) void k_cvtW(const float* __restrict__ src) {
    const size_t i = (size_t)blockIdx.x * 256 + threadIdx.x;
    float4 v = ((const float4*)src)[i];
    uint2 h, l;
    cvt2(v, h, l);
    ((uint2*)g_Wh)[i] = h;
    ((uint2*)g_Wl)[i] = l;
}

// ---------------------------------------------------------------------------
// Kernel 1: wf = X @ W^T + bias via mma.sync bf16 hi/lo split (3 passes).
// Proven LDT=40 layout/geometry + cp.async 2-stage double buffer.
// Race fix vs R5: __syncthreads at END of loop body so next iteration's
// cp.async never overwrites a buffer still being read by ldmatrix.
// Stage: Ah|Al|Bh|Bl, each 128*LDT*2 = 10240 B -> 40960 B; 2 stages = 80 KB.
// ---------------------------------------------------------------------------
#define LDT 40
#define ARR_B   (128 * LDT * 2)       // 10240
#define STG_B   (4 * ARR_B)           // 40960
#define GEMM_SMEM (2 * STG_B)         // 81920

__global__ __launch_bounds__(256) void k_gemm_mma(const float* __restrict__ bias) {
    extern __shared__ char sm[];
    const uint32_t sb = smem_u32(sm);

    const int tid = threadIdx.x, lane = tid & 31, wid = tid >> 5;
    const int m0 = blockIdx.y * 128, n0 = blockIdx.x * 128;
    const int wm = (wid >> 1) * 32, wn = (wid & 1) * 64;

    const __nv_bfloat16* srcs[4] = {
        g_Xh + (size_t)m0 * CC, g_Xl + (size_t)m0 * CC,
        g_Wh + (size_t)n0 * CC, g_Wl + (size_t)n0 * CC};

    const int lrow = tid >> 2;        // 0..63
    const int lc = tid & 3;           // 16B chunk 0..3

    auto load_stage = [&](int stg, int k0) {
        const uint32_t base = sb + stg * STG_B;
#pragma unroll
        for (int a = 0; a < 4; a++) {
#pragma unroll
            for (int it = 0; it < 2; it++) {
                const int row = lrow + it * 64;
                cpa16(base + a * ARR_B + (uint32_t)(row * (LDT * 2) + lc * 16),
                      srcs[a] + (size_t)row * CC + k0 + lc * 8);
            }
        }
    };

    // ldmatrix per-lane byte offsets (identical geometry to R4/R7)
    const int lr = lane & 15, kc = (lane >> 4) << 3;             // A: row, col
    const uint32_t a_l = (uint32_t)(((wm + lr) * LDT + kc) * 2);
    const int br = (lane & 7) + ((lane >> 4) << 3);              // B: row
    const int bk = ((lane >> 3) & 1) << 3;                       // B: col
    const uint32_t b_l = (uint32_t)(((wn + br) * LDT + bk) * 2);

    float acc[2][8][4];
#pragma unroll
    for (int i = 0; i < 2; i++)
#pragma unroll
        for (int j = 0; j < 8; j++)
#pragma unroll
            for (int q = 0; q < 4; q++) acc[i][j][q] = 0.f;

    load_stage(0, 0);
    CPA_COMMIT();

#pragma unroll 1
    for (int ch = 0; ch < 16; ch++) {
        if (ch < 15) {
            load_stage((ch + 1) & 1, (ch + 1) * 32);
            CPA_COMMIT();
            CPA_WAIT(1);          // current stage's group complete
        } else {
            CPA_WAIT(0);
        }
        __syncthreads();

        const uint32_t sAh_b = sb + (ch & 1) * STG_B;
        const uint32_t sAl_b = sAh_b + ARR_B;
        const uint32_t sBh_b = sAh_b + 2 * ARR_B;
        const uint32_t sBl_b = sAh_b + 3 * ARR_B;

#pragma unroll
        for (int s = 0; s < 2; s++) {
            uint32_t Ah[2][4], Al[2][4];
#pragma unroll
            for (int i = 0; i < 2; i++) {
                const uint32_t off = a_l + (uint32_t)(i * 16 * LDT * 2 + s * 32);
                ldsm4(Ah[i], sAh_b + off);
                ldsm4(Al[i], sAl_b + off);
            }
#pragma unroll
            for (int g = 0; g < 4; g++) {
                const uint32_t off = b_l + (uint32_t)(g * 16 * LDT * 2 + s * 32);
                uint32_t Bh[4], Bl[4];
                ldsm4(Bh, sBh_b + off);
                ldsm4(Bl, sBl_b + off);
#pragma unroll
                for (int i = 0; i < 2; i++) {
                    mma16816(acc[i][2 * g],     Ah[i], Bh[0], Bh[1]);
                    mma16816(acc[i][2 * g + 1], Ah[i], Bh[2], Bh[3]);
                    mma16816(acc[i][2 * g],     Ah[i], Bl[0], Bl[1]);
                    mma16816(acc[i][2 * g + 1], Ah[i], Bl[2], Bl[3]);
                    mma16816(acc[i][2 * g],     Al[i], Bh[0], Bh[1]);
                    mma16816(acc[i][2 * g + 1], Al[i], Bh[2], Bh[3]);
                }
            }
        }
        __syncthreads();   // RACE FIX: next iter's cp.async targets the buffer
                           // computed from two iterations ago — all reads done.
    }

    const int cr = lane >> 2, cc2 = (lane & 3) * 2;
#pragma unroll
    for (int i = 0; i < 2; i++) {
        const int m = m0 + wm + i * 16 + cr;
#pragma unroll
        for (int j = 0; j < 8; j++) {
            const int n = n0 + wn + j * 8 + cc2;
            float2 bv = *(const float2*)&bias[n];
            *(float2*)&g_wf[(size_t)m * CC + n] =
                make_float2(acc[i][j][0] + bv.x, acc[i][j][1] + bv.y);
            *(float2*)&g_wf[(size_t)(m + 8) * CC + n] =
                make_float2(acc[i][j][2] + bv.x, acc[i][j][3] + bv.y);
        }
    }
}

// ---------------------------------------------------------------------------
// Kernel 2: scores[b,l,t] = sum_c tanh(wf[b,t,c] + pos[l,c]) * aw[c]
// Group-4 deferred reductions (R10 structure) + launch_bounds(256,4) to cap
// regs at 64 -> 4 CTAs/SM. atten_b dropped (softmax shift-invariant).
// ---------------------------------------------------------------------------
__device__ __forceinline__ float tanh_hw(float x) {
    float y;
    asm("tanh.approx.f32 %0, %1;" : "=f"(y) : "f"(x));
    return y;
}

__global__ __launch_bounds__(256, 4) void k_scores(const float* __restrict__ pos,
                                                   const float* __restrict__ aw) {
    __shared__ __align__(16) float sp[16 * CC];   // rows >= nl are junk, never stored

    const int tid = threadIdx.x;
    const int b = blockIdx.x;
    const int tch = blockIdx.y;
    const int l0 = blockIdx.z * 13;
    const int nl = blockIdx.z ? 12 : 13;
    const int warp = tid >> 5, lane = tid & 31;

    for (int i = tid; i < nl * CC; i += 256) sp[i] = pos[l0 * CC + i];
    __syncthreads();

    float4 wv[4];
#pragma unroll
    for (int g = 0; g < 4; g++)
        wv[g] = *(const float4*)&aw[g * 128 + lane * 4];

    for (int tt = 0; tt < 4; tt++) {
        const int t = tch * 32 + warp * 4 + tt;
        const float* wrow = &g_wf[((size_t)b * TT + t) * CC];
        float4 fv[4];
#pragma unroll
        for (int g = 0; g < 4; g++)
            fv[g] = *(const float4*)&wrow[g * 128 + lane * 4];

        float* srow = &g_scores[((size_t)b * LL + l0) * TT + t];

#pragma unroll 1
        for (int lg = 0; lg < nl; lg += 4) {
            float acc[4] = {0.f, 0.f, 0.f, 0.f};
#pragma unroll
            for (int u = 0; u < 4; u++) {
                const float* prow = &sp[(lg + u) * CC];
                float a = 0.f;
#pragma unroll
                for (int g = 0; g < 4; g++) {
                    float4 p = *(const float4*)&prow[g * 128 + lane * 4];
                    a += tanh_hw(fv[g].x + p.x) * wv[g].x;
                    a += tanh_hw(fv[g].y + p.y) * wv[g].y;
                    a += tanh_hw(fv[g].z + p.z) * wv[g].z;
                    a += tanh_hw(fv[g].w + p.w) * wv[g].w;
                }
                acc[u] = a;
            }
#pragma unroll
            for (int o = 16; o > 0; o >>= 1)
#pragma unroll
                for (int u = 0; u < 4; u++)
                    acc[u] += __shfl_xor_sync(0xFFFFFFFFu, acc[u], o);
#pragma unroll
            for (int u = 0; u < 4; u++)
                if (lg + u < nl && lane == u)
                    srow[(size_t)(lg + u) * TT] = acc[u];
        }
    }
}

// ---------------------------------------------------------------------------
// Kernel 3: in-place softmax over t.
// ---------------------------------------------------------------------------
__global__ __launch_bounds__(256) void k_softmax() {
    __shared__ float red[8];
    __shared__ float red2[8];
    const int row = blockIdx.x;
    float* s = g_scores + (size_t)row * TT;
    const int tid = threadIdx.x, lane = tid & 31, w = tid >> 5;

    float v = s[tid];
    float m = v;
#pragma unroll
    for (int o = 16; o > 0; o >>= 1)
        m = fmaxf(m, __shfl_xor_sync(0xFFFFFFFFu, m, o));
    if (lane == 0) red[w] = m;
    __syncthreads();
    float bm = red[0];
#pragma unroll
    for (int i = 1; i < 8; i++) bm = fmaxf(bm, red[i]);

    float e = __expf(v - bm);
    float sum = e;
#pragma unroll
    for (int o = 16; o > 0; o >>= 1)
        sum += __shfl_xor_sync(0xFFFFFFFFu, sum, o);
    if (lane == 0) red2[w] = sum;
    __syncthreads();
    float tot = 0.f;
#pragma unroll
    for (int i = 0; i < 8; i++) tot += red2[i];

    s[tid] = e / tot;
}

// ---------------------------------------------------------------------------
// Kernel 4a: pvam partials, 8-way t-split, float2 lanes + packed f32x2 FMA.
// ---------------------------------------------------------------------------
__global__ __launch_bounds__(256) void k_pvam1() {
    __shared__ __align__(8) float2 at2[LL][32];   // (a,a) pairs
    const int b = blockIdx.x, s = blockIdx.y;
    const int tid = threadIdx.x;

    for (int i = tid; i < LL * 32; i += 256) {
        const int l = i >> 5, j = i & 31;
        const float a = g_scores[((size_t)b * LL + l) * TT + s * 32 + j];
        at2[l][j] = make_float2(a, a);
    }
    __syncthreads();

    unsigned long long acc[LL];
#pragma unroll
    for (int l = 0; l < LL; l++) acc[l] = 0ull;

    const unsigned long long* at2u = (const unsigned long long*)at2;
    const unsigned long long* wb = (const unsigned long long*)
        (&g_wf[((size_t)b * TT + s * 32) * CC]) + tid;

#pragma unroll 4
    for (int j = 0; j < 32; j++) {
        const unsigned long long v = wb[(size_t)j * (CC / 2)];
#pragma unroll
        for (int l = 0; l < LL; l++)
            asm("fma.rn.f32x2 %0, %1, %2, %0;"
                : "+l"(acc[l]) : "l"(at2u[l * 32 + j]), "l"(v));
    }

    unsigned long long* pp = (unsigned long long*)
        (&g_part[(size_t)s * BB * LL * CC + (size_t)b * LL * CC]) + tid;
#pragma unroll
    for (int l = 0; l < LL; l++) pp[(size_t)l * (CC / 2)] = acc[l];
}

// Kernel 4b: sum the 8 partials -> out.
__global__ __launch_bounds__(256) void k_pvam2(float* __restrict__ out) {
    const size_t N = (size_t)BB * LL * CC;
    size_t i = (size_t)blockIdx.x * 256 + threadIdx.x;
    float a = 0.f;
#pragma unroll
    for (int s = 0; s < 8; s++) a += g_part[s * N + i];
    out[i] = a;
}

// ---------------------------------------------------------------------------
extern "C" void kernel_launch(void* const* d_in, const int* in_sizes, int n_in,
                              void* d_out, int out_size) {
    const float* X    = (const float*)d_in[0];
    const float* W    = (const float*)d_in[1];
    const float* bias = (const float*)d_in[2];
    const float* pos  = (const float*)d_in[3];
    const float* aw   = (const float*)d_in[4];
    float* out = (float*)d_out;

    cudaFuncSetAttribute(k_gemm_mma, cudaFuncAttributeMaxDynamicSharedMemorySize,
                         GEMM_SMEM);

    k_cvtX<<<MM * CC / 4 / 256, 256>>>(X);
    k_cvtW<<<CC * CC / 4 / 256, 256>>>(W);
    k_gemm_mma<<<dim3(CC / 128, MM / 128), 256, GEMM_SMEM>>>(bias);
    k_scores<<<dim3(BB, TT / 32, 2), 256>>>(pos, aw);
    k_softmax<<<BB * LL, 256>>>();
    k_pvam1<<<dim3(BB, 8), 256>>>();
    k_pvam2<<<BB * LL * CC / 256, 256>>>(out);
}

// round 15
// speedup vs baseline: 1.2948x; 1.0569x over previous
#include <cuda_runtime.h>
#include <cuda_bf16.h>
#include <cuda_fp16.h>
#include <cstdint>

#define BB 32
#define TT 256
#define CC 512
#define LL 25
#define MM (BB*TT)   // 8192

// Scratch (device globals — no runtime allocation allowed)
__device__ float g_wf[(size_t)MM * CC];            // 16 MB
__device__ __align__(4) __half g_wf16[(size_t)MM * CC]; // 8.4 MB packed half
__device__ float g_scores[(size_t)BB * LL * TT];   // 0.8 MB
__device__ float g_part[(size_t)8 * BB * LL * CC]; // 13 MB pvam partials
__device__ __align__(16) __nv_bfloat16 g_Xh[(size_t)MM * CC];
__device__ __align__(16) __nv_bfloat16 g_Xl[(size_t)MM * CC];
__device__ __align__(16) __nv_bfloat16 g_Wh[(size_t)CC * CC];
__device__ __align__(16) __nv_bfloat16 g_Wl[(size_t)CC * CC];

// ---------------------------------------------------------------------------
// Helpers
// ---------------------------------------------------------------------------
__device__ __forceinline__ uint32_t smem_u32(const void* p) {
    uint32_t a;
    asm("{ .reg .u64 t; cvta.to.shared.u64 t, %1; cvt.u32.u64 %0, t; }"
        : "=r"(a) : "l"(p));
    return a;
}
__device__ __forceinline__ void ldsm4(uint32_t* r, uint32_t addr) {
    asm volatile("ldmatrix.sync.aligned.m8n8.x4.shared.b16 {%0,%1,%2,%3}, [%4];"
                 : "=r"(r[0]), "=r"(r[1]), "=r"(r[2]), "=r"(r[3]) : "r"(addr));
}
__device__ __forceinline__ void mma16816(float* d, const uint32_t* a,
                                         uint32_t b0, uint32_t b1) {
    asm volatile(
        "mma.sync.aligned.m16n8k16.row.col.f32.bf16.bf16.f32 "
        "{%0,%1,%2,%3}, {%4,%5,%6,%7}, {%8,%9}, {%0,%1,%2,%3};"
        : "+f"(d[0]), "+f"(d[1]), "+f"(d[2]), "+f"(d[3])
        : "r"(a[0]), "r"(a[1]), "r"(a[2]), "r"(a[3]), "r"(b0), "r"(b1));
}
__device__ __forceinline__ void cpa16(uint32_t s, const void* g) {
    asm volatile("cp.async.cg.shared.global [%0], [%1], 16;"
                 :: "r"(s), "l"(g) : "memory");
}
#define CPA_COMMIT() asm volatile("cp.async.commit_group;" ::: "memory")
#define CPA_WAIT(n)  asm volatile("cp.async.wait_group %0;" :: "n"(n) : "memory")

// fp32 -> bf16 hi + bf16 lo (residual), packed as bf16x2 words
__device__ __forceinline__ void cvt2(float4 v, uint2& hi, uint2& lo) {
    __nv_bfloat162 h01 = __floats2bfloat162_rn(v.x, v.y);
    __nv_bfloat162 h23 = __floats2bfloat162_rn(v.z, v.w);
    float2 f01 = __bfloat1622float2(h01);
    float2 f23 = __bfloat1622float2(h23);
    __nv_bfloat162 l01 = __floats2bfloat162_rn(v.x - f01.x, v.y - f01.y);
    __nv_bfloat162 l23 = __floats2bfloat162_rn(v.z - f23.x, v.w - f23.y);
    hi.x = *reinterpret_cast<uint32_t*>(&h01);
    hi.y = *reinterpret_cast<uint32_t*>(&h23);
    lo.x = *reinterpret_cast<uint32_t*>(&l01);
    lo.y = *reinterpret_cast<uint32_t*>(&l23);
}

// ---------------------------------------------------------------------------
// Kernel 0: fp32 -> bf16 hi/lo prepass (globals referenced in device code only
// — host-passed __device__ symbols hit the ATS host-shadow bug).
// ---------------------------------------------------------------------------
__global__ __launch_bounds__(256) void k_cvtX(const float* __restrict__ src) {
    const size_t i = (size_t)blockIdx.x * 256 + threadIdx.x;
    float4 v = ((const float4*)src)[i];
    uint2 h, l;
    cvt2(v, h, l);
    ((uint2*)g_Xh)[i] = h;
    ((uint2*)g_Xl)[i] = l;
}
__global__ __launch_bounds__(256) void k_cvtW(const float* __restrict__ src) {
    const size_t i = (size_t)blockIdx.x * 256 + threadIdx.x;
    float4 v = ((const float4*)src)[i];
    uint2 h, l;
    cvt2(v, h, l);
    ((uint2*)g_Wh)[i] = h;
    ((uint2*)g_Wl)[i] = l;
}

// ---------------------------------------------------------------------------
// Kernel 1: wf = X @ W^T + bias, mma.sync bf16 hi/lo (3 passes), cp.async
// 2-stage double buffer (race-fixed). Epilogue stores fp32 AND packed half2.
// ---------------------------------------------------------------------------
#define LDT 40
#define ARR_B   (128 * LDT * 2)       // 10240
#define STG_B   (4 * ARR_B)           // 40960
#define GEMM_SMEM (2 * STG_B)         // 81920

__global__ __launch_bounds__(256) void k_gemm_mma(const float* __restrict__ bias) {
    extern __shared__ char sm[];
    const uint32_t sb = smem_u32(sm);

    const int tid = threadIdx.x, lane = tid & 31, wid = tid >> 5;
    const int m0 = blockIdx.y * 128, n0 = blockIdx.x * 128;
    const int wm = (wid >> 1) * 32, wn = (wid & 1) * 64;

    const __nv_bfloat16* srcs[4] = {
        g_Xh + (size_t)m0 * CC, g_Xl + (size_t)m0 * CC,
        g_Wh + (size_t)n0 * CC, g_Wl + (size_t)n0 * CC};

    const int lrow = tid >> 2;        // 0..63
    const int lc = tid & 3;           // 16B chunk 0..3

    auto load_stage = [&](int stg, int k0) {
        const uint32_t base = sb + stg * STG_B;
#pragma unroll
        for (int a = 0; a < 4; a++) {
#pragma unroll
            for (int it = 0; it < 2; it++) {
                const int row = lrow + it * 64;
                cpa16(base + a * ARR_B + (uint32_t)(row * (LDT * 2) + lc * 16),
                      srcs[a] + (size_t)row * CC + k0 + lc * 8);
            }
        }
    };

    const int lr = lane & 15, kc = (lane >> 4) << 3;
    const uint32_t a_l = (uint32_t)(((wm + lr) * LDT + kc) * 2);
    const int br = (lane & 7) + ((lane >> 4) << 3);
    const int bk = ((lane >> 3) & 1) << 3;
    const uint32_t b_l = (uint32_t)(((wn + br) * LDT + bk) * 2);

    float acc[2][8][4];
#pragma unroll
    for (int i = 0; i < 2; i++)
#pragma unroll
        for (int j = 0; j < 8; j++)
#pragma unroll
            for (int q = 0; q < 4; q++) acc[i][j][q] = 0.f;

    load_stage(0, 0);
    CPA_COMMIT();

#pragma unroll 1
    for (int ch = 0; ch < 16; ch++) {
        if (ch < 15) {
            load_stage((ch + 1) & 1, (ch + 1) * 32);
            CPA_COMMIT();
            CPA_WAIT(1);
        } else {
            CPA_WAIT(0);
        }
        __syncthreads();

        const uint32_t sAh_b = sb + (ch & 1) * STG_B;
        const uint32_t sAl_b = sAh_b + ARR_B;
        const uint32_t sBh_b = sAh_b + 2 * ARR_B;
        const uint32_t sBl_b = sAh_b + 3 * ARR_B;

#pragma unroll
        for (int s = 0; s < 2; s++) {
            uint32_t Ah[2][4], Al[2][4];
#pragma unroll
            for (int i = 0; i < 2; i++) {
                const uint32_t off = a_l + (uint32_t)(i * 16 * LDT * 2 + s * 32);
                ldsm4(Ah[i], sAh_b + off);
                ldsm4(Al[i], sAl_b + off);
            }
#pragma unroll
            for (int g = 0; g < 4; g++) {
                const uint32_t off = b_l + (uint32_t)(g * 16 * LDT * 2 + s * 32);
                uint32_t Bh[4], Bl[4];
                ldsm4(Bh, sBh_b + off);
                ldsm4(Bl, sBl_b + off);
#pragma unroll
                for (int i = 0; i < 2; i++) {
                    mma16816(acc[i][2 * g],     Ah[i], Bh[0], Bh[1]);
                    mma16816(acc[i][2 * g + 1], Ah[i], Bh[2], Bh[3]);
                    mma16816(acc[i][2 * g],     Ah[i], Bl[0], Bl[1]);
                    mma16816(acc[i][2 * g + 1], Ah[i], Bl[2], Bl[3]);
                    mma16816(acc[i][2 * g],     Al[i], Bh[0], Bh[1]);
                    mma16816(acc[i][2 * g + 1], Al[i], Bh[2], Bh[3]);
                }
            }
        }
        __syncthreads();
    }

    const int cr = lane >> 2, cc2 = (lane & 3) * 2;
#pragma unroll
    for (int i = 0; i < 2; i++) {
        const int m = m0 + wm + i * 16 + cr;
#pragma unroll
        for (int j = 0; j < 8; j++) {
            const int n = n0 + wn + j * 8 + cc2;
            float2 bv = *(const float2*)&bias[n];
            const float a0 = acc[i][j][0] + bv.x, a1 = acc[i][j][1] + bv.y;
            const float a2 = acc[i][j][2] + bv.x, a3 = acc[i][j][3] + bv.y;
            *(float2*)&g_wf[(size_t)m * CC + n] = make_float2(a0, a1);
            *(float2*)&g_wf[(size_t)(m + 8) * CC + n] = make_float2(a2, a3);
            *(__half2*)&g_wf16[(size_t)m * CC + n] = __floats2half2_rn(a0, a1);
            *(__half2*)&g_wf16[(size_t)(m + 8) * CC + n] = __floats2half2_rn(a2, a3);
        }
    }
}

// ---------------------------------------------------------------------------
// Kernel 2: scores[b,l,t] = sum_c tanh(wf[b,t,c] + pos[l,c]) * aw[c]
// f16x2 path: wf half2 from g_wf16 (regs, reused over l), pos half2 in smem,
// HADD2 + tanh.approx.f16x2 (MUFU halved), fp32 accumulation via H2F+FFMA.
// Group-4 deferred butterfly reductions. atten_b dropped (shift-invariant).
// ---------------------------------------------------------------------------
__device__ __forceinline__ uint32_t tanh2_hw(uint32_t x) {
    uint32_t y;
    asm("tanh.approx.f16x2 %0, %1;" : "=r"(y) : "r"(x));
    return y;
}

__global__ __launch_bounds__(256, 4) void k_scores(const float* __restrict__ pos,
                                                   const float* __restrict__ aw) {
    __shared__ __align__(16) __half sp16[16 * CC];   // 16 KB

    const int tid = threadIdx.x;
    const int b = blockIdx.x;
    const int tch = blockIdx.y;
    const int l0 = blockIdx.z * 13;
    const int nl = blockIdx.z ? 12 : 13;
    const int warp = tid >> 5, lane = tid & 31;

    for (int i = tid; i < nl * CC / 2; i += 256) {
        float2 p = ((const float2*)(pos + l0 * CC))[i];
        ((__half2*)sp16)[i] = __floats2half2_rn(p.x, p.y);
    }
    __syncthreads();

    float4 wv[4];
#pragma unroll
    for (int g = 0; g < 4; g++)
        wv[g] = *(const float4*)&aw[g * 128 + lane * 4];

    for (int tt = 0; tt < 4; tt++) {
        const int t = tch * 32 + warp * 4 + tt;
        const __half* wrow = &g_wf16[((size_t)b * TT + t) * CC];
        uint2 fv[4];   // 4 groups x 4 halfs (2 half2 words)
#pragma unroll
        for (int g = 0; g < 4; g++)
            fv[g] = *(const uint2*)&wrow[g * 128 + lane * 4];

        float* srow = &g_scores[((size_t)b * LL + l0) * TT + t];

#pragma unroll 1
        for (int lg = 0; lg < nl; lg += 4) {
            float acc[4] = {0.f, 0.f, 0.f, 0.f};
#pragma unroll
            for (int u = 0; u < 4; u++) {
                const __half* prow = &sp16[(lg + u) * CC];
                float a = 0.f;
#pragma unroll
                for (int g = 0; g < 4; g++) {
                    uint2 p = *(const uint2*)&prow[g * 128 + lane * 4];
                    const __half2 s01 = __hadd2(*(const __half2*)&fv[g].x,
                                                *(const __half2*)&p.x);
                    const __half2 s23 = __hadd2(*(const __half2*)&fv[g].y,
                                                *(const __half2*)&p.y);
                    const uint32_t t01 = tanh2_hw(*(const uint32_t*)&s01);
                    const uint32_t t23 = tanh2_hw(*(const uint32_t*)&s23);
                    const float2 f01 = __half22float2(*(const __half2*)&t01);
                    const float2 f23 = __half22float2(*(const __half2*)&t23);
                    a += f01.x * wv[g].x;
                    a += f01.y * wv[g].y;
                    a += f23.x * wv[g].z;
                    a += f23.y * wv[g].w;
                }
                acc[u] = a;
            }
#pragma unroll
            for (int o = 16; o > 0; o >>= 1)
#pragma unroll
                for (int u = 0; u < 4; u++)
                    acc[u] += __shfl_xor_sync(0xFFFFFFFFu, acc[u], o);
#pragma unroll
            for (int u = 0; u < 4; u++)
                if (lg + u < nl && lane == u)
                    srow[(size_t)(lg + u) * TT] = acc[u];
        }
    }
}

// ---------------------------------------------------------------------------
// Kernel 3: in-place softmax over t.
// ---------------------------------------------------------------------------
__global__ __launch_bounds__(256) void k_softmax() {
    __shared__ float red[8];
    __shared__ float red2[8];
    const int row = blockIdx.x;
    float* s = g_scores + (size_t)row * TT;
    const int tid = threadIdx.x, lane = tid & 31, w = tid >> 5;

    float v = s[tid];
    float m = v;
#pragma unroll
    for (int o = 16; o > 0; o >>= 1)
        m = fmaxf(m, __shfl_xor_sync(0xFFFFFFFFu, m, o));
    if (lane == 0) red[w] = m;
    __syncthreads();
    float bm = red[0];
#pragma unroll
    for (int i = 1; i < 8; i++) bm = fmaxf(bm, red[i]);

    float e = __expf(v - bm);
    float sum = e;
#pragma unroll
    for (int o = 16; o > 0; o >>= 1)
        sum += __shfl_xor_sync(0xFFFFFFFFu, sum, o);
    if (lane == 0) red2[w] = sum;
    __syncthreads();
    float tot = 0.f;
#pragma unroll
    for (int i = 0; i < 8; i++) tot += red2[i];

    s[tid] = e / tot;
}

// ---------------------------------------------------------------------------
// Kernel 4a: pvam partials, 8-way t-split, float2 lanes + packed f32x2 FMA.
// ---------------------------------------------------------------------------
__global__ __launch_bounds__(256) void k_pvam1() {
    __shared__ __align__(8) float2 at2[LL][32];   // (a,a) pairs
    const int b = blockIdx.x, s = blockIdx.y;
    const int tid = threadIdx.x;

    for (int i = tid; i < LL * 32; i += 256) {
        const int l = i >> 5, j = i & 31;
        const float a = g_scores[((size_t)b * LL + l) * TT + s * 32 + j];
        at2[l][j] = make_float2(a, a);
    }
    __syncthreads();

    unsigned long long acc[LL];
#pragma unroll
    for (int l = 0; l < LL; l++) acc[l] = 0ull;

    const unsigned long long* at2u = (const unsigned long long*)at2;
    const unsigned long long* wb = (const unsigned long long*)
        (&g_wf[((size_t)b * TT + s * 32) * CC]) + tid;

#pragma unroll 4
    for (int j = 0; j < 32; j++) {
        const unsigned long long v = wb[(size_t)j * (CC / 2)];
#pragma unroll
        for (int l = 0; l < LL; l++)
            asm("fma.rn.f32x2 %0, %1, %2, %0;"
                : "+l"(acc[l]) : "l"(at2u[l * 32 + j]), "l"(v));
    }

    unsigned long long* pp = (unsigned long long*)
        (&g_part[(size_t)s * BB * LL * CC + (size_t)b * LL * CC]) + tid;
#pragma unroll
    for (int l = 0; l < LL; l++) pp[(size_t)l * (CC / 2)] = acc[l];
}

// Kernel 4b: sum the 8 partials -> out.
__global__ __launch_bounds__(256) void k_pvam2(float* __restrict__ out) {
    const size_t N = (size_t)BB * LL * CC;
    size_t i = (size_t)blockIdx.x * 256 + threadIdx.x;
    float a = 0.f;
#pragma unroll
    for (int s = 0; s < 8; s++) a += g_part[s * N + i];
    out[i] = a;
}

// ---------------------------------------------------------------------------
extern "C" void kernel_launch(void* const* d_in, const int* in_sizes, int n_in,
                              void* d_out, int out_size) {
    const float* X    = (const float*)d_in[0];
    const float* W    = (const float*)d_in[1];
    const float* bias = (const float*)d_in[2];
    const float* pos  = (const float*)d_in[3];
    const float* aw   = (const float*)d_in[4];
    float* out = (float*)d_out;

    cudaFuncSetAttribute(k_gemm_mma, cudaFuncAttributeMaxDynamicSharedMemorySize,
                         GEMM_SMEM);

    k_cvtX<<<MM * CC / 4 / 256, 256>>>(X);
    k_cvtW<<<CC * CC / 4 / 256, 256>>>(W);
    k_gemm_mma<<<dim3(CC / 128, MM / 128), 256, GEMM_SMEM>>>(bias);
    k_scores<<<dim3(BB, TT / 32, 2), 256>>>(pos, aw);
    k_softmax<<<BB * LL, 256>>>();
    k_pvam1<<<dim3(BB, 8), 256>>>();
    k_pvam2<<<BB * LL * CC / 256, 256>>>(out);
}